// round 16
// baseline (speedup 1.0000x reference)
#include <cuda_runtime.h>
#include <cuda_fp16.h>
#include <math.h>

// ---------------------------------------------------------------------------
// FloorPlanLoss: B=1024 batches, R=192 rooms.
//  out[0]=total, out[1]=pos_mse, out[2]=size_mse, out[3]=overlap, out[4]=adjacency
//
// Block b = (batch pair p=b>>1, k-half h=b&1).  Batches 2p,2p+1 packed half2
// for overlap; adjacency distance scalar fp32 (exact centers), predicated on a
// prebuilt transposed bitmask; per-block MSE; last-block finalize.
// ---------------------------------------------------------------------------

#define B 1024
#define R 192
#define NTILES 6
#define NUNITS 21
#define NTHREADS 256
#define NWARPS 8

// Packed (t, c) for the 21 triangular chunk-units, 3 bits each (octal digits,
// unit u = digit u from the right).  t: 0 1 1 2 2 2 3 3 3 3 4 4 4 4 4 5 5 5 5 5 5
//                                    c: 0 0 1 0 1 2 0 1 2 3 0 1 2 3 4 0 1 2 3 4 5
#define TPACK 0555555444443333222110ULL
#define CPACK 0543210432103210210100ULL

// Transposed adjacency bitmask: g_adjT[c*192 + j] bit k set iff
//   i = 32c+k,  i < j,  adj[0][i][j] > 0
__device__ unsigned int g_adjT[NTILES * R];
__device__ float        g_partials[B * 4];
__device__ int          g_done;          // zero-init; last block resets to 0

__device__ __forceinline__ float fsqrt_approx(float x)
{
    float r;
    asm("sqrt.approx.f32 %0, %1;" : "=f"(r) : "f"(x));
    return r;
}

__device__ __forceinline__ __half2 u_as_h2(unsigned v)
{
    return *reinterpret_cast<__half2*>(&v);
}
__device__ __forceinline__ unsigned h2_as_u(__half2 v)
{
    return *reinterpret_cast<unsigned*>(&v);
}

// ---------------------------------------------------------------------------
// Kernel 1: warp-ballot transposed adjacency build.
// grid = 36 blocks (c = i-chunk, jt = j-tile), 32 threads (one warp).
// ---------------------------------------------------------------------------
__global__ __launch_bounds__(32)
void build_adjT_kernel(const int* __restrict__ adj)
{
    const int c    = blockIdx.x / NTILES;
    const int jt   = blockIdx.x % NTILES;
    const int lane = threadIdx.x;
    const int j    = jt * 32 + lane;

    unsigned ball[32];
    #pragma unroll
    for (int k = 0; k < 32; k++) {
        int i = c * 32 + k;
        int v = adj[i * R + j];                      // coalesced 128B per warp
        ball[k] = __ballot_sync(0xffffffffu, (j > i) && (v > 0));
    }
    unsigned bits = 0;
    #pragma unroll
    for (int k = 0; k < 32; k++)
        bits |= ((ball[k] >> lane) & 1u) << k;
    g_adjT[c * R + j] = bits;
}

// ---------------------------------------------------------------------------
// Pair-loop body (16 iterations of one k-half).
//   rec:  uint4 (hi_x2, hi_y2, nlo_x2, nlo_y2) — half2, batch pair packed
//   ctr:  float4 (cx0, cy0, cx1, cy1) — fp32 centers (scalar math, no packing)
// awh/lth are pre-shifted by 16h so bit kk maps to k_eff = kk + 16h.
// ncj* are the NEGATED centers of room j (FADD with register constants).
// ---------------------------------------------------------------------------
template <bool DIAG>
__device__ __forceinline__ void unit_body(const uint4* __restrict__ recp,
                                          const float4* __restrict__ ctrp,
                                          __half2 hjx2, __half2 hjy2,
                                          __half2 njx2, __half2 njy2,
                                          float ncjx0, float ncjy0,
                                          float ncjx1, float ncjy1,
                                          unsigned awh, unsigned lth,
                                          __half2& ov2, float& ad0, float& ad1)
{
    const __half2 z2 = __half2half2(__ushort_as_half(0));
    #pragma unroll
    for (int kk = 0; kk < 16; kk++) {
        uint4 rv = recp[kk];                         // LDS.128 broadcast
        __half2 mx = __hmin2(u_as_h2(rv.x), hjx2);
        __half2 my = __hmin2(u_as_h2(rv.y), hjy2);
        __half2 nx = __hmin2(u_as_h2(rv.z), njx2);
        __half2 ny = __hmin2(u_as_h2(rv.w), njy2);
        __half2 owx = __hmax2(__hadd2(mx, nx), z2);
        __half2 owy = __hmax2(__hadd2(my, ny), z2);
        if (DIAG) {
            __half2 term = __hmul2(owx, owy);
            if (lth & (1u << kk)) ov2 = __hadd2(ov2, term);   // k_eff < lane
        } else {
            ov2 = __hfma2(owx, owy, ov2);
        }
        float4 cv = ctrp[kk];                        // LDS.128 broadcast
        float dx0 = cv.x + ncjx0;
        float dy0 = cv.y + ncjy0;
        float dx1 = cv.z + ncjx1;
        float dy1 = cv.w + ncjy1;
        float q0 = fsqrt_approx(fmaf(dx0, dx0, dy0 * dy0));
        float q1 = fsqrt_approx(fmaf(dx1, dx1, dy1 * dy1));
        if (awh & (1u << kk)) { ad0 += q0; ad1 += q1; }
    }
}

// ---------------------------------------------------------------------------
// Kernel 2 (fused): per-batch MSE + pairwise terms + last-block finalize.
// ---------------------------------------------------------------------------
__global__ __launch_bounds__(NTHREADS, 7)
void floorplan_main_kernel(const float* __restrict__ pos,
                           const float* __restrict__ siz,
                           const float* __restrict__ tpos,
                           const float* __restrict__ tsiz,
                           float* __restrict__ out)
{
    __shared__ uint4  s_rec[R];          // (hi_x2, hi_y2, nlo_x2, nlo_y2) half2
    __shared__ float4 s_ctr[R];          // (cx0, cy0, cx1, cy1) fp32
    __shared__ float  s_red[NWARPS][4];
    __shared__ bool   s_last;

    const int b    = blockIdx.x;
    const int p    = b >> 1;             // batch pair
    const int h    = b & 1;              // k-half
    const int b0   = p * 2;
    const int b1   = p * 2 + 1;
    const int tid  = threadIdx.x;
    const int lane = tid & 31;
    const int warp = tid >> 5;
    const int kshift = h << 4;           // 0 or 16

    // --- unit schedule (rotated by pair so SMSP load averages out) ---
    const int base = (warp + p) & 7;
    unsigned aw[3];
    #pragma unroll
    for (int s = 0; s < 3; s++) {
        int u = base + 8 * s;
        if (u < NUNITS) {
            int t = (int)((TPACK >> (3 * u)) & 7);
            int c = (int)((CPACK >> (3 * u)) & 7);
            aw[s] = __ldg(&g_adjT[c * R + t * 32 + lane]) >> kshift;
        } else aw[s] = 0;
    }

    // --- load both batches' rooms, build packed records, own-batch MSE ---
    const float2* p0 = (const float2*)pos  + (size_t)b0 * R;
    const float2* s0 = (const float2*)siz  + (size_t)b0 * R;
    const float2* p1 = (const float2*)pos  + (size_t)b1 * R;
    const float2* s1 = (const float2*)siz  + (size_t)b1 * R;
    const float2* tpo = (const float2*)tpos + (size_t)b * R;
    const float2* tso = (const float2*)tsiz + (size_t)b * R;

    float mse_pos = 0.f, mse_size = 0.f;
    if (tid < R) {
        float2 xy0 = p0[tid], wh0 = s0[tid];
        float2 xy1 = p1[tid], wh1 = s1[tid];
        uint4 rec;
        rec.x = h2_as_u(__floats2half2_rn(xy0.x + wh0.x, xy1.x + wh1.x));
        rec.y = h2_as_u(__floats2half2_rn(xy0.y + wh0.y, xy1.y + wh1.y));
        rec.z = h2_as_u(__floats2half2_rn(-xy0.x, -xy1.x));
        rec.w = h2_as_u(__floats2half2_rn(-xy0.y, -xy1.y));
        s_rec[tid] = rec;
        s_ctr[tid] = make_float4(xy0.x + 0.5f * wh0.x, xy0.y + 0.5f * wh0.y,
                                 xy1.x + 0.5f * wh1.x, xy1.y + 0.5f * wh1.y);
        // own-batch MSE
        float2 oxy = h ? xy1 : xy0;
        float2 owh = h ? wh1 : wh0;
        float2 txy = tpo[tid];
        float2 twh = tso[tid];
        float dpx = oxy.x - txy.x, dpy = oxy.y - txy.y;
        float dsx = owh.x - twh.x, dsy = owh.y - twh.y;
        mse_pos  = fmaf(dpx, dpx, dpy * dpy);
        mse_size = fmaf(dsx, dsx, dsy * dsy);
    }
    __syncthreads();

    // --- pairwise loop: lane owns column j; broadcast row i (k-half h) ---
    float ovf0 = 0.f, ovf1 = 0.f, ad0 = 0.f, ad1 = 0.f;
    const unsigned lth = (((1u << lane) - 1u) >> kshift);  // bit kk: kk+16h < lane

    #pragma unroll
    for (int s = 0; s < 3; s++) {
        int u = base + 8 * s;
        if (u >= NUNITS) break;                      // warp-uniform
        const int t = (int)((TPACK >> (3 * u)) & 7);
        const int c = (int)((CPACK >> (3 * u)) & 7);
        const int j = t * 32 + lane;
        uint4  rj = s_rec[j];
        float4 cj = s_ctr[j];
        const uint4*  recp = s_rec + c * 32 + kshift;
        const float4* ctrp = s_ctr + c * 32 + kshift;

        __half2 ov2 = __half2half2(__ushort_as_half(0));
        if (c < t)
            unit_body<false>(recp, ctrp, u_as_h2(rj.x), u_as_h2(rj.y),
                             u_as_h2(rj.z), u_as_h2(rj.w),
                             -cj.x, -cj.y, -cj.z, -cj.w,
                             aw[s], lth, ov2, ad0, ad1);
        else
            unit_body<true>(recp, ctrp, u_as_h2(rj.x), u_as_h2(rj.y),
                            u_as_h2(rj.z), u_as_h2(rj.w),
                            -cj.x, -cj.y, -cj.z, -cj.w,
                            aw[s], lth, ov2, ad0, ad1);
        ovf0 += __low2float(ov2);                    // flush per unit (16 terms)
        ovf1 += __high2float(ov2);
    }

    // --- block reduction (deterministic fixed tree) ---
    float v0 = mse_pos, v1 = mse_size, v2 = ovf0 + ovf1, v3 = ad0 + ad1;
    #pragma unroll
    for (int off = 16; off > 0; off >>= 1) {
        v0 += __shfl_xor_sync(0xffffffffu, v0, off);
        v1 += __shfl_xor_sync(0xffffffffu, v1, off);
        v2 += __shfl_xor_sync(0xffffffffu, v2, off);
        v3 += __shfl_xor_sync(0xffffffffu, v3, off);
    }
    if (lane == 0) {
        s_red[warp][0] = v0; s_red[warp][1] = v1;
        s_red[warp][2] = v2; s_red[warp][3] = v3;
    }
    __syncthreads();
    if (tid == 0) {
        float a0 = 0.f, a1 = 0.f, a2 = 0.f, a3 = 0.f;
        #pragma unroll
        for (int w = 0; w < NWARPS; w++) {
            a0 += s_red[w][0]; a1 += s_red[w][1];
            a2 += s_red[w][2]; a3 += s_red[w][3];
        }
        g_partials[b * 4 + 0] = a0;
        g_partials[b * 4 + 1] = a1;
        g_partials[b * 4 + 2] = a2;
        g_partials[b * 4 + 3] = a3;
    }

    // --- last-block finalize ---
    __threadfence();
    if (tid == 0)
        s_last = (atomicAdd(&g_done, 1) == B - 1);
    __syncthreads();
    if (!s_last) return;
    __threadfence();

    float r0 = 0.f, r1 = 0.f, r2 = 0.f, r3 = 0.f;
    for (int bb = tid; bb < B; bb += NTHREADS) {
        r0 += g_partials[bb * 4 + 0];
        r1 += g_partials[bb * 4 + 1];
        r2 += g_partials[bb * 4 + 2];
        r3 += g_partials[bb * 4 + 3];
    }
    #pragma unroll
    for (int off = 16; off > 0; off >>= 1) {
        r0 += __shfl_xor_sync(0xffffffffu, r0, off);
        r1 += __shfl_xor_sync(0xffffffffu, r1, off);
        r2 += __shfl_xor_sync(0xffffffffu, r2, off);
        r3 += __shfl_xor_sync(0xffffffffu, r3, off);
    }
    if (lane == 0) {
        s_red[warp][0] = r0; s_red[warp][1] = r1;
        s_red[warp][2] = r2; s_red[warp][3] = r3;
    }
    __syncthreads();
    if (tid == 0) {
        float a0 = 0.f, a1 = 0.f, a2 = 0.f, a3 = 0.f;
        #pragma unroll
        for (int w = 0; w < NWARPS; w++) {
            a0 += s_red[w][0]; a1 += s_red[w][1];
            a2 += s_red[w][2]; a3 += s_red[w][3];
        }
        const float inv_mse = 1.0f / (float)(B * R * 2);
        const float inv_b   = 1.0f / (float)B;
        float pos_loss = a0 * inv_mse;
        float siz_loss = a1 * inv_mse;
        float ov_loss  = a2 * inv_b;
        float ad_loss  = a3 * inv_b;
        out[0] = pos_loss + siz_loss + 0.5f * ov_loss + 0.3f * ad_loss;
        out[1] = pos_loss;
        out[2] = siz_loss;
        out[3] = ov_loss;
        out[4] = ad_loss;
        g_done = 0;                       // restore for next graph replay
    }
}

// ---------------------------------------------------------------------------
extern "C" void kernel_launch(void* const* d_in, const int* in_sizes, int n_in,
                              void* d_out, int out_size)
{
    const float* pos  = (const float*)d_in[0];   // position_updates [B,R,2]
    const float* siz  = (const float*)d_in[1];   // size_updates     [B,R,2]
    const float* tpos = (const float*)d_in[2];   // target_positions [B,R,2]
    const float* tsiz = (const float*)d_in[3];   // target_sizes     [B,R,2]
    const int*   adj  = (const int*)d_in[4];     // adjacency_matrix [1,R,R]
    float* out = (float*)d_out;

    build_adjT_kernel<<<NTILES * NTILES, 32>>>(adj);
    floorplan_main_kernel<<<B, NTHREADS>>>(pos, siz, tpos, tsiz, out);
}

// round 17
// speedup vs baseline: 1.1568x; 1.1568x over previous
#include <cuda_runtime.h>
#include <cuda_fp16.h>
#include <math.h>

// ---------------------------------------------------------------------------
// FloorPlanLoss: B=1024 batches, R=192 rooms.
//  out[0]=total, out[1]=pos_mse, out[2]=size_mse, out[3]=overlap, out[4]=adjacency
//
// Block b = (batch pair p=b>>1, k-half h=b&1).  Batches 2p,2p+1 packed half2
// for overlap; adjacency distance fp32 (f32x2 packed), predicated on a
// prebuilt transposed bitmask; per-block MSE; last-block finalize.
// ---------------------------------------------------------------------------

#define B 1024
#define R 192
#define NTILES 6
#define NUNITS 21
#define NTHREADS 256
#define NWARPS 8

// Packed (t, c) for the 21 triangular chunk-units, 3 bits each (octal digits,
// unit u = digit u from the right).  t: 0 1 1 2 2 2 3 3 3 3 4 4 4 4 4 5 5 5 5 5 5
//                                    c: 0 0 1 0 1 2 0 1 2 3 0 1 2 3 4 0 1 2 3 4 5
#define TPACK 0555555444443333222110ULL
#define CPACK 0543210432103210210100ULL

// Transposed adjacency bitmask: g_adjT[c*192 + j] bit k set iff
//   i = 32c+k,  i < j,  adj[0][i][j] > 0
__device__ unsigned int g_adjT[NTILES * R];
__device__ float        g_partials[B * 4];
__device__ int          g_done;          // zero-init; last block resets to 0

__device__ __forceinline__ float fsqrt_approx(float x)
{
    float r;
    asm("sqrt.approx.f32 %0, %1;" : "=f"(r) : "f"(x));
    return r;
}

__device__ __forceinline__ unsigned long long pack_f32x2(float lo, float hi)
{
    unsigned long long r;
    asm("mov.b64 %0, {%1, %2};" : "=l"(r) : "f"(lo), "f"(hi));
    return r;
}

__device__ __forceinline__ void unpack_f32x2(unsigned long long v, float& lo, float& hi)
{
    asm("mov.b64 {%0, %1}, %2;" : "=f"(lo), "=f"(hi) : "l"(v));
}

__device__ __forceinline__ unsigned long long add_f32x2(unsigned long long a,
                                                        unsigned long long b)
{
    unsigned long long r;
    asm("add.rn.f32x2 %0, %1, %2;" : "=l"(r) : "l"(a), "l"(b));
    return r;
}

__device__ __forceinline__ __half2 u_as_h2(unsigned v)
{
    return *reinterpret_cast<__half2*>(&v);
}
__device__ __forceinline__ unsigned h2_as_u(__half2 v)
{
    return *reinterpret_cast<unsigned*>(&v);
}

// ---------------------------------------------------------------------------
// Kernel 1: warp-ballot transposed adjacency build.
// grid = 36 blocks (c = i-chunk, jt = j-tile), 32 threads (one warp).
// ---------------------------------------------------------------------------
__global__ __launch_bounds__(32)
void build_adjT_kernel(const int* __restrict__ adj)
{
    const int c    = blockIdx.x / NTILES;
    const int jt   = blockIdx.x % NTILES;
    const int lane = threadIdx.x;
    const int j    = jt * 32 + lane;

    unsigned ball[32];
    #pragma unroll
    for (int k = 0; k < 32; k++) {
        int i = c * 32 + k;
        int v = adj[i * R + j];                      // coalesced 128B per warp
        ball[k] = __ballot_sync(0xffffffffu, (j > i) && (v > 0));
    }
    unsigned bits = 0;
    #pragma unroll
    for (int k = 0; k < 32; k++)
        bits |= ((ball[k] >> lane) & 1u) << k;
    g_adjT[c * R + j] = bits;
}

// ---------------------------------------------------------------------------
// Pair-loop body (16 iterations of one k-half).
//   rec:  uint4 (hi_x2, hi_y2, nlo_x2, nlo_y2) — half2, batch pair packed
//   ctr:  ulonglong2 ((cx0,cy0),(cx1,cy1)) — fp32 centers
// awh/lth are pre-shifted by 16h so bit kk maps to k_eff = kk + 16h.
// Dual overlap accumulators break the HFMA2 dependency chain.
// ---------------------------------------------------------------------------
template <bool DIAG>
__device__ __forceinline__ void unit_body(const uint4* __restrict__ recp,
                                          const ulonglong2* __restrict__ ctrp,
                                          __half2 hjx2, __half2 hjy2,
                                          __half2 njx2, __half2 njy2,
                                          unsigned long long ncj0,
                                          unsigned long long ncj1,
                                          unsigned awh, unsigned lth,
                                          __half2& ov2a, __half2& ov2b,
                                          float& ad0, float& ad1)
{
    const __half2 z2 = __half2half2(__ushort_as_half(0));
    #pragma unroll
    for (int kk = 0; kk < 16; kk++) {
        uint4      rv = recp[kk];                    // LDS.128 broadcast
        ulonglong2 cv = ctrp[kk];                    // LDS.128 broadcast (issue早)
        __half2 mx = __hmin2(u_as_h2(rv.x), hjx2);
        __half2 my = __hmin2(u_as_h2(rv.y), hjy2);
        __half2 nx = __hmin2(u_as_h2(rv.z), njx2);
        __half2 ny = __hmin2(u_as_h2(rv.w), njy2);
        __half2 owx = __hmax2(__hadd2(mx, nx), z2);
        __half2 owy = __hmax2(__hadd2(my, ny), z2);
        if (DIAG) {
            __half2 term = __hmul2(owx, owy);
            if (lth & (1u << kk)) {
                if (kk & 1) ov2b = __hadd2(ov2b, term);
                else        ov2a = __hadd2(ov2a, term);
            }
        } else {
            if (kk & 1) ov2b = __hfma2(owx, owy, ov2b);
            else        ov2a = __hfma2(owx, owy, ov2a);
        }
        unsigned long long d0 = add_f32x2(cv.x, ncj0);
        unsigned long long d1 = add_f32x2(cv.y, ncj1);
        float dx0, dy0, dx1, dy1;
        unpack_f32x2(d0, dx0, dy0);
        unpack_f32x2(d1, dx1, dy1);
        float q0 = fsqrt_approx(fmaf(dx0, dx0, dy0 * dy0));
        float q1 = fsqrt_approx(fmaf(dx1, dx1, dy1 * dy1));
        if (awh & (1u << kk)) { ad0 += q0; ad1 += q1; }
    }
}

// ---------------------------------------------------------------------------
// Kernel 2 (fused): per-batch MSE + pairwise terms + last-block finalize.
// ---------------------------------------------------------------------------
__global__ __launch_bounds__(NTHREADS, 7)
void floorplan_main_kernel(const float* __restrict__ pos,
                           const float* __restrict__ siz,
                           const float* __restrict__ tpos,
                           const float* __restrict__ tsiz,
                           float* __restrict__ out)
{
    __shared__ uint4  s_rec[R];          // (hi_x2, hi_y2, nlo_x2, nlo_y2) half2
    __shared__ float4 s_ctr[R];          // (cx0, cy0, cx1, cy1) fp32
    __shared__ float  s_red[NWARPS][4];
    __shared__ bool   s_last;

    const int b    = blockIdx.x;
    const int p    = b >> 1;             // batch pair
    const int h    = b & 1;              // k-half
    const int b0   = p * 2;
    const int b1   = p * 2 + 1;
    const int tid  = threadIdx.x;
    const int lane = tid & 31;
    const int warp = tid >> 5;
    const int kshift = h << 4;           // 0 or 16

    // --- unit schedule (rotated by pair so SMSP load averages out) ---
    const int base = (warp + p) & 7;
    unsigned aw[3];
    #pragma unroll
    for (int s = 0; s < 3; s++) {
        int u = base + 8 * s;
        if (u < NUNITS) {
            int t = (int)((TPACK >> (3 * u)) & 7);
            int c = (int)((CPACK >> (3 * u)) & 7);
            aw[s] = __ldg(&g_adjT[c * R + t * 32 + lane]) >> kshift;
        } else aw[s] = 0;
    }

    // --- load both batches' rooms, build packed records, own-batch MSE ---
    const float2* p0 = (const float2*)pos  + (size_t)b0 * R;
    const float2* s0 = (const float2*)siz  + (size_t)b0 * R;
    const float2* p1 = (const float2*)pos  + (size_t)b1 * R;
    const float2* s1 = (const float2*)siz  + (size_t)b1 * R;
    const float2* tpo = (const float2*)tpos + (size_t)b * R;
    const float2* tso = (const float2*)tsiz + (size_t)b * R;

    float mse_pos = 0.f, mse_size = 0.f;
    if (tid < R) {
        float2 xy0 = p0[tid], wh0 = s0[tid];
        float2 xy1 = p1[tid], wh1 = s1[tid];
        uint4 rec;
        rec.x = h2_as_u(__floats2half2_rn(xy0.x + wh0.x, xy1.x + wh1.x));
        rec.y = h2_as_u(__floats2half2_rn(xy0.y + wh0.y, xy1.y + wh1.y));
        rec.z = h2_as_u(__floats2half2_rn(-xy0.x, -xy1.x));
        rec.w = h2_as_u(__floats2half2_rn(-xy0.y, -xy1.y));
        s_rec[tid] = rec;
        s_ctr[tid] = make_float4(xy0.x + 0.5f * wh0.x, xy0.y + 0.5f * wh0.y,
                                 xy1.x + 0.5f * wh1.x, xy1.y + 0.5f * wh1.y);
        // own-batch MSE
        float2 oxy = h ? xy1 : xy0;
        float2 owh = h ? wh1 : wh0;
        float2 txy = tpo[tid];
        float2 twh = tso[tid];
        float dpx = oxy.x - txy.x, dpy = oxy.y - txy.y;
        float dsx = owh.x - twh.x, dsy = owh.y - twh.y;
        mse_pos  = fmaf(dpx, dpx, dpy * dpy);
        mse_size = fmaf(dsx, dsx, dsy * dsy);
    }
    __syncthreads();

    // --- pairwise loop: lane owns column j; broadcast row i (k-half h) ---
    float ovf0 = 0.f, ovf1 = 0.f, ad0 = 0.f, ad1 = 0.f;
    const unsigned lth = (((1u << lane) - 1u) >> kshift);  // bit kk: kk+16h < lane

    #pragma unroll
    for (int s = 0; s < 3; s++) {
        int u = base + 8 * s;
        if (u >= NUNITS) break;                      // warp-uniform
        const int t = (int)((TPACK >> (3 * u)) & 7);
        const int c = (int)((CPACK >> (3 * u)) & 7);
        const int j = t * 32 + lane;
        uint4  rj = s_rec[j];
        float4 cj = s_ctr[j];
        unsigned long long ncj0 = pack_f32x2(-cj.x, -cj.y);
        unsigned long long ncj1 = pack_f32x2(-cj.z, -cj.w);
        const uint4*      recp = s_rec + c * 32 + kshift;
        const ulonglong2* ctrp = (const ulonglong2*)s_ctr + c * 32 + kshift;

        __half2 ov2a = __half2half2(__ushort_as_half(0));
        __half2 ov2b = __half2half2(__ushort_as_half(0));
        if (c < t)
            unit_body<false>(recp, ctrp, u_as_h2(rj.x), u_as_h2(rj.y),
                             u_as_h2(rj.z), u_as_h2(rj.w),
                             ncj0, ncj1, aw[s], lth, ov2a, ov2b, ad0, ad1);
        else
            unit_body<true>(recp, ctrp, u_as_h2(rj.x), u_as_h2(rj.y),
                            u_as_h2(rj.z), u_as_h2(rj.w),
                            ncj0, ncj1, aw[s], lth, ov2a, ov2b, ad0, ad1);
        ovf0 += __low2float(ov2a) + __low2float(ov2b);    // flush per unit
        ovf1 += __high2float(ov2a) + __high2float(ov2b);
    }

    // --- block reduction (deterministic fixed tree) ---
    float v0 = mse_pos, v1 = mse_size, v2 = ovf0 + ovf1, v3 = ad0 + ad1;
    #pragma unroll
    for (int off = 16; off > 0; off >>= 1) {
        v0 += __shfl_xor_sync(0xffffffffu, v0, off);
        v1 += __shfl_xor_sync(0xffffffffu, v1, off);
        v2 += __shfl_xor_sync(0xffffffffu, v2, off);
        v3 += __shfl_xor_sync(0xffffffffu, v3, off);
    }
    if (lane == 0) {
        s_red[warp][0] = v0; s_red[warp][1] = v1;
        s_red[warp][2] = v2; s_red[warp][3] = v3;
    }
    __syncthreads();
    if (tid == 0) {
        float a0 = 0.f, a1 = 0.f, a2 = 0.f, a3 = 0.f;
        #pragma unroll
        for (int w = 0; w < NWARPS; w++) {
            a0 += s_red[w][0]; a1 += s_red[w][1];
            a2 += s_red[w][2]; a3 += s_red[w][3];
        }
        g_partials[b * 4 + 0] = a0;
        g_partials[b * 4 + 1] = a1;
        g_partials[b * 4 + 2] = a2;
        g_partials[b * 4 + 3] = a3;
    }

    // --- last-block finalize ---
    __threadfence();
    if (tid == 0)
        s_last = (atomicAdd(&g_done, 1) == B - 1);
    __syncthreads();
    if (!s_last) return;
    __threadfence();

    float r0 = 0.f, r1 = 0.f, r2 = 0.f, r3 = 0.f;
    for (int bb = tid; bb < B; bb += NTHREADS) {
        r0 += g_partials[bb * 4 + 0];
        r1 += g_partials[bb * 4 + 1];
        r2 += g_partials[bb * 4 + 2];
        r3 += g_partials[bb * 4 + 3];
    }
    #pragma unroll
    for (int off = 16; off > 0; off >>= 1) {
        r0 += __shfl_xor_sync(0xffffffffu, r0, off);
        r1 += __shfl_xor_sync(0xffffffffu, r1, off);
        r2 += __shfl_xor_sync(0xffffffffu, r2, off);
        r3 += __shfl_xor_sync(0xffffffffu, r3, off);
    }
    if (lane == 0) {
        s_red[warp][0] = r0; s_red[warp][1] = r1;
        s_red[warp][2] = r2; s_red[warp][3] = r3;
    }
    __syncthreads();
    if (tid == 0) {
        float a0 = 0.f, a1 = 0.f, a2 = 0.f, a3 = 0.f;
        #pragma unroll
        for (int w = 0; w < NWARPS; w++) {
            a0 += s_red[w][0]; a1 += s_red[w][1];
            a2 += s_red[w][2]; a3 += s_red[w][3];
        }
        const float inv_mse = 1.0f / (float)(B * R * 2);
        const float inv_b   = 1.0f / (float)B;
        float pos_loss = a0 * inv_mse;
        float siz_loss = a1 * inv_mse;
        float ov_loss  = a2 * inv_b;
        float ad_loss  = a3 * inv_b;
        out[0] = pos_loss + siz_loss + 0.5f * ov_loss + 0.3f * ad_loss;
        out[1] = pos_loss;
        out[2] = siz_loss;
        out[3] = ov_loss;
        out[4] = ad_loss;
        g_done = 0;                       // restore for next graph replay
    }
}

// ---------------------------------------------------------------------------
extern "C" void kernel_launch(void* const* d_in, const int* in_sizes, int n_in,
                              void* d_out, int out_size)
{
    const float* pos  = (const float*)d_in[0];   // position_updates [B,R,2]
    const float* siz  = (const float*)d_in[1];   // size_updates     [B,R,2]
    const float* tpos = (const float*)d_in[2];   // target_positions [B,R,2]
    const float* tsiz = (const float*)d_in[3];   // target_sizes     [B,R,2]
    const int*   adj  = (const int*)d_in[4];     // adjacency_matrix [1,R,R]
    float* out = (float*)d_out;

    build_adjT_kernel<<<NTILES * NTILES, 32>>>(adj);
    floorplan_main_kernel<<<B, NTHREADS>>>(pos, siz, tpos, tsiz, out);
}